// round 2
// baseline (speedup 1.0000x reference)
#include <cuda_runtime.h>
#include <cstddef>
#include <cstdint>

// SparseConv: out[out_map[k,m]] += x[in_map[k,m]] @ W[k]   (K=27, M=65536, Cin=Cout=64)
//
// Inputs (metadata order):
//   d_in[0] = x       float32 [N, 64]
//   d_in[1] = W       float32 [K, 64, 64]
//   d_in[2] = in_map  int32   [K, M]
//   d_in[3] = out_map int32   [K, M]
// Output: float32 [N, 64]
//
// Strategy (round 1 baseline): one CTA per (k, 128-edge tile).
//   smem: W[k] (64x64 f32), gathered X tile (128 x 65 padded f32), edge index lists.
//   Register-blocked fp32 GEMM: 256 threads as 16x16 grid, 8x4 micro-tile each.
//   Scatter via vectorized red.global.add.v4.f32 (4x fewer RED ops than scalar).

#define EDGES   128
#define THREADS 256
#define CIN     64
#define COUT    64
#define XPAD    65   // 128*65 stride: row diff 8*65 = 520 = 8 mod 32 -> conflict-free col reads

// dynamic smem layout (floats):
//   Ws   : [0, 4096)            W[k], row-major [cin][cout]
//   Xs   : [4096, 4096+128*65)  gathered rows, [edge][cin] padded
//   idx  : ints after that: inidx[128], outidx[128]
#define SMEM_FLOATS (4096 + EDGES * XPAD + 2 * EDGES)
#define SMEM_BYTES  (SMEM_FLOATS * 4)

__global__ __launch_bounds__(THREADS) void sparse_conv_kernel(
    const float* __restrict__ x,
    const float* __restrict__ W,
    const int*   __restrict__ in_map,
    const int*   __restrict__ out_map,
    float*       __restrict__ out,
    int M)
{
    extern __shared__ float smem[];
    float* Ws = smem;                      // 4096 floats
    float* Xs = smem + 4096;               // 128 * 65 floats
    int*   inidx  = (int*)(smem + 4096 + EDGES * XPAD);
    int*   outidx = inidx + EDGES;

    const int k   = blockIdx.y;
    const int m0  = blockIdx.x * EDGES;
    const int tid = threadIdx.x;

    // --- load edge index lists ---
    if (tid < EDGES) {
        const int m = m0 + tid;
        inidx[tid]  = in_map[(size_t)k * M + m];
        outidx[tid] = out_map[(size_t)k * M + m];
    }

    // --- load W[k] (4096 floats = 1024 float4, 4 per thread) ---
    {
        const float4* Wv = reinterpret_cast<const float4*>(W + (size_t)k * (CIN * COUT));
        float4* Wsv = reinterpret_cast<float4*>(Ws);
        #pragma unroll
        for (int i = 0; i < 4; i++)
            Wsv[tid + i * THREADS] = Wv[tid + i * THREADS];
    }
    __syncthreads();

    // --- gather x rows: 128 rows * 16 float4 = 2048 float4, 8 per thread ---
    #pragma unroll
    for (int j = 0; j < (EDGES * 16) / THREADS; j++) {
        const int f = tid + j * THREADS;
        const int e = f >> 4;
        const int q = f & 15;
        const float4 v = reinterpret_cast<const float4*>(x + (size_t)inidx[e] * CIN)[q];
        float* dst = &Xs[e * XPAD + q * 4];
        dst[0] = v.x; dst[1] = v.y; dst[2] = v.z; dst[3] = v.w;
    }
    __syncthreads();

    // --- GEMM: [128 x 64] = Xs[128 x 64] @ Ws[64 x 64] ---
    // thread (ty, tx): rows ty*8 .. ty*8+7, cols tx*4 .. tx*4+3
    const int tx = tid & 15;
    const int ty = tid >> 4;

    float acc[8][4];
    #pragma unroll
    for (int i = 0; i < 8; i++)
        #pragma unroll
        for (int j = 0; j < 4; j++)
            acc[i][j] = 0.0f;

    #pragma unroll 8
    for (int kk = 0; kk < CIN; kk++) {
        const float4 b = *reinterpret_cast<const float4*>(&Ws[kk * COUT + tx * 4]);
        float a[8];
        #pragma unroll
        for (int i = 0; i < 8; i++)
            a[i] = Xs[(ty * 8 + i) * XPAD + kk];
        #pragma unroll
        for (int i = 0; i < 8; i++) {
            acc[i][0] += a[i] * b.x;
            acc[i][1] += a[i] * b.y;
            acc[i][2] += a[i] * b.z;
            acc[i][3] += a[i] * b.w;
        }
    }

    // --- scatter-add: vectorized RED (no return) into L2-resident out ---
    #pragma unroll
    for (int i = 0; i < 8; i++) {
        const int r = ty * 8 + i;
        float* dst = out + (size_t)outidx[r] * COUT + tx * 4;
        asm volatile(
            "red.global.add.v4.f32 [%0], {%1, %2, %3, %4};"
            :: "l"(dst), "f"(acc[i][0]), "f"(acc[i][1]), "f"(acc[i][2]), "f"(acc[i][3])
            : "memory");
    }
}

extern "C" void kernel_launch(void* const* d_in, const int* in_sizes, int n_in,
                              void* d_out, int out_size)
{
    const float* x       = (const float*)d_in[0];
    const float* W       = (const float*)d_in[1];
    const int*   in_map  = (const int*)d_in[2];
    const int*   out_map = (const int*)d_in[3];
    float*       out     = (float*)d_out;

    const int K = in_sizes[1] / (CIN * COUT);   // 27
    const int M = in_sizes[2] / K;              // 65536

    static bool attr_set = false;
    if (!attr_set) {
        cudaFuncSetAttribute(sparse_conv_kernel,
                             cudaFuncAttributeMaxDynamicSharedMemorySize, SMEM_BYTES);
        attr_set = true;
    }

    // d_out is poisoned; zero it (graph-capturable memset node), then accumulate.
    cudaMemsetAsync(d_out, 0, (size_t)out_size * sizeof(float), 0);

    dim3 grid(M / EDGES, K);
    sparse_conv_kernel<<<grid, THREADS, SMEM_BYTES>>>(x, W, in_map, out_map, out, M);
}

// round 4
// speedup vs baseline: 1.4326x; 1.4326x over previous
#include <cuda_runtime.h>
#include <cuda_bf16.h>
#include <cstddef>
#include <cstdint>

// SparseConv: out[out_map[k,m]] += x[in_map[k,m]] @ W[k]   (K=27, M=65536, Cin=Cout=64)
//
// Round 4: warp-level bf16 mma.sync (compute_100-safe; tcgen05 rejected by harness's
// virtual arch). 3-term hi/lo bf16 split for fp32 accuracy (~1.5e-5 rel err).
//   CTA = (k, 128-edge tile). Warp w: rows 16w..16w+15, all 64 output cols.
//   A (hi/lo) in smem (stride 144B, conflict-free ldmatrix), B = W[k] hi/lo in smem.
//   96 x mma.m16n8k16 per warp per tile. Epilogue: shfl pair-swap -> red.global.add.v4.

#define CIN     64
#define COUT    64
#define EDGES   128
#define THREADS 256
#define CTAS_X  21

#define STRIDE_A 144   // bytes per A row (64 bf16 = 128B data + 16B pad; rows step 4 banks)
#define STRIDE_B 144

#define SM_A_HI  0
#define SM_A_LO  (EDGES * STRIDE_A)            // 18432
#define SM_B_HI  (2 * EDGES * STRIDE_A)        // 36864
#define SM_B_LO  (SM_B_HI + CIN * STRIDE_B)    // 46080
#define SM_TOTAL (SM_B_LO + CIN * STRIDE_B)    // 55296 bytes

__device__ __forceinline__ uint32_t smem_u32(const void* p) {
    uint32_t a;
    asm("{ .reg .u64 t; cvta.to.shared.u64 t, %1; cvt.u32.u64 %0, t; }" : "=r"(a) : "l"(p));
    return a;
}
__device__ __forceinline__ uint32_t pack_bf16x2(float hi_elem, float lo_elem) {
    uint32_t r;
    asm("cvt.rn.bf16x2.f32 %0, %1, %2;" : "=r"(r) : "f"(hi_elem), "f"(lo_elem));
    return r;  // [15:0]=bf16(lo_elem), [31:16]=bf16(hi_elem)
}

#define LDSM_X4(r, addr) \
    asm volatile("ldmatrix.sync.aligned.m8n8.x4.shared.b16 {%0,%1,%2,%3}, [%4];" \
        : "=r"((r)[0]), "=r"((r)[1]), "=r"((r)[2]), "=r"((r)[3]) : "r"(addr))

#define LDSM_X4_T(r, addr) \
    asm volatile("ldmatrix.sync.aligned.m8n8.x4.trans.shared.b16 {%0,%1,%2,%3}, [%4];" \
        : "=r"((r)[0]), "=r"((r)[1]), "=r"((r)[2]), "=r"((r)[3]) : "r"(addr))

#define MMA_BF16(c, a, b0, b1) \
    asm volatile("mma.sync.aligned.m16n8k16.row.col.f32.bf16.bf16.f32 " \
        "{%0,%1,%2,%3}, {%4,%5,%6,%7}, {%8,%9}, {%0,%1,%2,%3};" \
        : "+f"((c)[0]), "+f"((c)[1]), "+f"((c)[2]), "+f"((c)[3]) \
        : "r"((a)[0]), "r"((a)[1]), "r"((a)[2]), "r"((a)[3]), "r"(b0), "r"(b1))

__device__ __forceinline__ void red_add_v4(float* dst, float a, float b, float c, float d) {
    asm volatile("red.global.add.v4.f32 [%0], {%1, %2, %3, %4};"
                 :: "l"(dst), "f"(a), "f"(b), "f"(c), "f"(d) : "memory");
}

__global__ void __launch_bounds__(THREADS, 3) sparse_conv_mma(
    const float* __restrict__ x,
    const float* __restrict__ W,
    const int*   __restrict__ in_map,
    const int*   __restrict__ out_map,
    float*       __restrict__ out,
    int M)
{
    extern __shared__ char smem[];
    const uint32_t sb = smem_u32(smem);
    const int tid  = threadIdx.x;
    const int w    = tid >> 5;
    const int lane = tid & 31;
    const int k    = blockIdx.y;
    const int kM   = k * M;
    const int ntiles = M >> 7;

    // --- W[k] -> bf16 hi/lo in smem, layout [cin][cout] row-major, stride 144B ---
    {
        const float* Wk = W + (size_t)k * (CIN * COUT);
        #pragma unroll
        for (int i = 0; i < (CIN * COUT) / THREADS; i++) {
            const int lin = tid + i * THREADS;
            const int c = lin >> 6, n = lin & 63;
            const float wv = Wk[lin];
            const __nv_bfloat16 hv = __float2bfloat16(wv);
            const __nv_bfloat16 lv = __float2bfloat16(wv - __bfloat162float(hv));
            const uint32_t off = (uint32_t)(c * STRIDE_B + n * 2);
            *(__nv_bfloat16*)(smem + SM_B_HI + off) = hv;
            *(__nv_bfloat16*)(smem + SM_B_LO + off) = lv;
        }
    }
    __syncthreads();

    // lane-dependent ldmatrix base addresses
    // A (non-trans): lane L -> row (16w + L%16), byte col (L/16)*16 (+ s*32 per k-step)
    const uint32_t a_off = (uint32_t)((16 * w + (lane & 15)) * STRIDE_A + (lane >> 4) * 16);
    const uint32_t aHi = sb + SM_A_HI + a_off;
    const uint32_t aLo = sb + SM_A_LO + a_off;
    // B (trans): lane L -> row (s*16 + L%16), byte col p*16 + (L/16)*16
    const uint32_t b_off = (uint32_t)((lane & 15) * STRIDE_B + (lane >> 4) * 16);
    const uint32_t bHi = sb + SM_B_HI + b_off;
    const uint32_t bLo = sb + SM_B_LO + b_off;

    // epilogue mapping: even lane emits row r, cols q0..q0+3; odd lane emits row r+8
    const int erow = 16 * w + (lane >> 2) + ((lane & 1) ? 8 : 0);
    const int q0   = (lane & 2) * 2;

    for (int mt = blockIdx.x; mt < ntiles; mt += gridDim.x) {
        const int m0 = mt * EDGES;

        // --- gather 128 rows of x, split fp32 -> bf16 hi/lo ---
        #pragma unroll
        for (int j = 0; j < (EDGES * 16) / THREADS; j++) {
            const int f = tid + j * THREADS;
            const int e = f >> 4;     // edge row (16 lanes share -> broadcast LDG)
            const int q = f & 15;     // float4 chunk
            const int row = in_map[kM + m0 + e];
            const float4 v = *(const float4*)(x + (size_t)row * CIN + q * 4);
            const uint32_t h0 = pack_bf16x2(v.y, v.x);
            const uint32_t h1 = pack_bf16x2(v.w, v.z);
            const float r0 = v.x - __uint_as_float(h0 << 16);
            const float r1 = v.y - __uint_as_float(h0 & 0xFFFF0000u);
            const float r2 = v.z - __uint_as_float(h1 << 16);
            const float r3 = v.w - __uint_as_float(h1 & 0xFFFF0000u);
            const uint32_t l0 = pack_bf16x2(r1, r0);
            const uint32_t l1 = pack_bf16x2(r3, r2);
            const uint32_t off = (uint32_t)(e * STRIDE_A + q * 8);
            *(uint2*)(smem + SM_A_HI + off) = make_uint2(h0, h1);
            *(uint2*)(smem + SM_A_LO + off) = make_uint2(l0, l1);
        }
        const int orow = out_map[kM + m0 + erow];
        __syncthreads();

        // --- GEMM: 96 mma per warp (8 n-tiles x 4 k-steps x 3 terms) ---
        float acc[8][4];
        #pragma unroll
        for (int t = 0; t < 8; t++)
            #pragma unroll
            for (int j = 0; j < 4; j++) acc[t][j] = 0.0f;

        #pragma unroll
        for (int s = 0; s < 4; s++) {
            uint32_t ah[4], al[4];
            LDSM_X4(ah, aHi + s * 32);
            LDSM_X4(al, aLo + s * 32);
            #pragma unroll
            for (int p = 0; p < 4; p++) {
                uint32_t bh[4], bl[4];
                const uint32_t boff = (uint32_t)(s * 16 * STRIDE_B + p * 32);
                LDSM_X4_T(bh, bHi + boff);
                LDSM_X4_T(bl, bLo + boff);
                MMA_BF16(acc[2 * p],     ah, bh[0], bh[1]);
                MMA_BF16(acc[2 * p + 1], ah, bh[2], bh[3]);
                MMA_BF16(acc[2 * p],     ah, bl[0], bl[1]);
                MMA_BF16(acc[2 * p + 1], ah, bl[2], bl[3]);
                MMA_BF16(acc[2 * p],     al, bh[0], bh[1]);
                MMA_BF16(acc[2 * p + 1], al, bh[2], bh[3]);
            }
        }

        // --- epilogue: pair-swap via shfl -> v4 scatter-add ---
        {
            float* obase = out + (size_t)orow * COUT + q0;
            const bool odd = (lane & 1);
            #pragma unroll
            for (int t = 0; t < 8; t++) {
                const float t0 = __shfl_xor_sync(0xFFFFFFFFu, acc[t][0], 1);
                const float t1 = __shfl_xor_sync(0xFFFFFFFFu, acc[t][1], 1);
                const float t2 = __shfl_xor_sync(0xFFFFFFFFu, acc[t][2], 1);
                const float t3 = __shfl_xor_sync(0xFFFFFFFFu, acc[t][3], 1);
                const float v0 = odd ? t2 : acc[t][0];
                const float v1 = odd ? t3 : acc[t][1];
                const float v2 = odd ? acc[t][2] : t0;
                const float v3 = odd ? acc[t][3] : t1;
                red_add_v4(obase + 8 * t, v0, v1, v2, v3);
            }
        }
        __syncthreads();  // protect smem A before next tile's gather overwrites
    }
}

extern "C" void kernel_launch(void* const* d_in, const int* in_sizes, int n_in,
                              void* d_out, int out_size)
{
    const float* x       = (const float*)d_in[0];
    const float* W       = (const float*)d_in[1];
    const int*   in_map  = (const int*)d_in[2];
    const int*   out_map = (const int*)d_in[3];
    float*       out     = (float*)d_out;

    const int K = in_sizes[1] / (CIN * COUT);   // 27
    const int M = in_sizes[2] / K;              // 65536

    static bool attr_set = false;
    if (!attr_set) {
        cudaFuncSetAttribute(sparse_conv_mma,
                             cudaFuncAttributeMaxDynamicSharedMemorySize, SM_TOTAL);
        attr_set = true;
    }

    cudaMemsetAsync(d_out, 0, (size_t)out_size * sizeof(float), 0);

    dim3 grid(CTAS_X, K);
    sparse_conv_mma<<<grid, THREADS, SM_TOTAL>>>(x, W, in_map, out_map, out, M);
}

// round 5
// speedup vs baseline: 1.5378x; 1.0734x over previous
#include <cuda_runtime.h>
#include <cuda_bf16.h>
#include <cstddef>
#include <cstdint>

// SparseConv: out[out_map[k,m]] += x[in_map[k,m]] @ W[k]   (K=27, M=65536, Cin=Cout=64)
//
// Round 5: warp-level bf16 mma.sync, 3-term hi/lo split, with:
//   - B-hi fragments hoisted to registers (loaded once per CTA; warp = 32 rows x 32 cols)
//   - double-buffered A + software-pipelined gather (1 sync per tile)
//   - 270 resident CTAs (2/SM), each CTA owns one k and ~51 tiles

#define CIN     64
#define COUT    64
#define EDGES   128
#define THREADS 256
#define CTAS_X  10

#define STRIDE_A 144   // row stride: conflict-free ldmatrix phases
#define STRIDE_B 144

#define ABUF     (EDGES * STRIDE_A)        // 18432 bytes per (buf, hi/lo) plane
#define SM_B_HI  (4 * ABUF)                // 73728
#define SM_B_LO  (SM_B_HI + CIN * STRIDE_B)
#define SM_TOTAL (SM_B_LO + CIN * STRIDE_B)  // 92160 bytes -> 2 CTAs/SM

__device__ __forceinline__ uint32_t smem_u32(const void* p) {
    uint32_t a;
    asm("{ .reg .u64 t; cvta.to.shared.u64 t, %1; cvt.u32.u64 %0, t; }" : "=r"(a) : "l"(p));
    return a;
}
__device__ __forceinline__ uint32_t pack_bf16x2(float hi_elem, float lo_elem) {
    uint32_t r;
    asm("cvt.rn.bf16x2.f32 %0, %1, %2;" : "=r"(r) : "f"(hi_elem), "f"(lo_elem));
    return r;  // [15:0]=bf16(lo_elem), [31:16]=bf16(hi_elem)
}

#define LDSM_X4(r, addr) \
    asm volatile("ldmatrix.sync.aligned.m8n8.x4.shared.b16 {%0,%1,%2,%3}, [%4];" \
        : "=r"((r)[0]), "=r"((r)[1]), "=r"((r)[2]), "=r"((r)[3]) : "r"(addr))

#define LDSM_X4_T(r, addr) \
    asm volatile("ldmatrix.sync.aligned.m8n8.x4.trans.shared.b16 {%0,%1,%2,%3}, [%4];" \
        : "=r"((r)[0]), "=r"((r)[1]), "=r"((r)[2]), "=r"((r)[3]) : "r"(addr))

#define MMA_BF16(c, a, b0, b1) \
    asm volatile("mma.sync.aligned.m16n8k16.row.col.f32.bf16.bf16.f32 " \
        "{%0,%1,%2,%3}, {%4,%5,%6,%7}, {%8,%9}, {%0,%1,%2,%3};" \
        : "+f"((c)[0]), "+f"((c)[1]), "+f"((c)[2]), "+f"((c)[3]) \
        : "r"((a)[0]), "r"((a)[1]), "r"((a)[2]), "r"((a)[3]), "r"(b0), "r"(b1))

__device__ __forceinline__ void red_add_v4(float* dst, float a, float b, float c, float d) {
    asm volatile("red.global.add.v4.f32 [%0], {%1, %2, %3, %4};"
                 :: "l"(dst), "f"(a), "f"(b), "f"(c), "f"(d) : "memory");
}

// gather 128 x-rows of tile (base edge index m0), split fp32 -> bf16 hi/lo, into buffer b
__device__ __forceinline__ void gather_tile(
    char* smem, int b, const float* __restrict__ x,
    const int* __restrict__ in_map, int kMm0, int tid)
{
    char* hiA = smem + b * (2 * ABUF);
    char* loA = hiA + ABUF;
    #pragma unroll
    for (int j = 0; j < (EDGES * 16) / THREADS; j++) {
        const int f = tid + j * THREADS;
        const int e = f >> 4;
        const int q = f & 15;
        const int row = in_map[kMm0 + e];
        const float4 v = *(const float4*)(x + (size_t)row * CIN + q * 4);
        const uint32_t h0 = pack_bf16x2(v.y, v.x);
        const uint32_t h1 = pack_bf16x2(v.w, v.z);
        const float r0 = v.x - __uint_as_float(h0 << 16);
        const float r1 = v.y - __uint_as_float(h0 & 0xFFFF0000u);
        const float r2 = v.z - __uint_as_float(h1 << 16);
        const float r3 = v.w - __uint_as_float(h1 & 0xFFFF0000u);
        const uint32_t l0 = pack_bf16x2(r1, r0);
        const uint32_t l1 = pack_bf16x2(r3, r2);
        const uint32_t off = (uint32_t)(e * STRIDE_A + q * 8);
        *(uint2*)(hiA + off) = make_uint2(h0, h1);
        *(uint2*)(loA + off) = make_uint2(l0, l1);
    }
}

__global__ void __launch_bounds__(THREADS, 2) sparse_conv_mma2(
    const float* __restrict__ x,
    const float* __restrict__ W,
    const int*   __restrict__ in_map,
    const int*   __restrict__ out_map,
    float*       __restrict__ out,
    int M)
{
    extern __shared__ char smem[];
    const uint32_t sb = smem_u32(smem);
    const int tid  = threadIdx.x;
    const int w    = tid >> 5;
    const int lane = tid & 31;
    const int mg   = w >> 1;        // m-group: rows 32*mg .. 32*mg+31
    const int nh   = w & 1;         // n-half: cols 32*nh .. 32*nh+31
    const int k    = blockIdx.y;
    const int kM   = k * M;
    const int ntiles = M >> 7;

    // --- stage W[k] -> bf16 hi/lo in smem ---
    {
        const float* Wk = W + (size_t)k * (CIN * COUT);
        #pragma unroll
        for (int i = 0; i < (CIN * COUT) / THREADS; i++) {
            const int lin = tid + i * THREADS;
            const int c = lin >> 6, n = lin & 63;
            const float wv = Wk[lin];
            const __nv_bfloat16 hv = __float2bfloat16(wv);
            const __nv_bfloat16 lv = __float2bfloat16(wv - __bfloat162float(hv));
            const uint32_t off = (uint32_t)(c * STRIDE_B + n * 2);
            *(__nv_bfloat16*)(smem + SM_B_HI + off) = hv;
            *(__nv_bfloat16*)(smem + SM_B_LO + off) = lv;
        }
    }
    __syncthreads();

    // --- hoist B-hi fragments for this warp's 32 cols into registers ---
    // ldmatrix trans addressing: lane L -> row (L%16), col byte (L/16)*16
    const uint32_t b_off = (uint32_t)((lane & 15) * STRIDE_B + (lane >> 4) * 16 + nh * 64);
    uint32_t bhr[4][2][4];
    #pragma unroll
    for (int s = 0; s < 4; s++)
        #pragma unroll
        for (int p = 0; p < 2; p++)
            LDSM_X4_T(bhr[s][p], sb + SM_B_HI + b_off + (uint32_t)(s * 16 * STRIDE_B + p * 32));
    const uint32_t bLo = sb + SM_B_LO + b_off;

    // A ldmatrix base: lane L -> row (32*mg + L%16), col byte (L/16)*16
    const uint32_t a_off = (uint32_t)((32 * mg + (lane & 15)) * STRIDE_A + (lane >> 4) * 16);

    // epilogue lane mapping (same as R4, per n8 tile)
    const bool odd = (lane & 1);
    const int  er0 = 32 * mg + (lane >> 2) + (odd ? 8 : 0);
    const int  q0  = (lane & 2) * 2;

    int mt = blockIdx.x;
    gather_tile(smem, 0, x, in_map, kM + (mt << 7), tid);
    __syncthreads();
    int buf = 0;

    while (mt < ntiles) {
        const int nxt = mt + CTAS_X;
        // pipelined gather of next tile into other buffer (LDGs overlap this tile's MMA
        // via the 15 other resident warps)
        if (nxt < ntiles)
            gather_tile(smem, buf ^ 1, x, in_map, kM + (nxt << 7), tid);

        // --- MMA: 2 m-tiles x 4 k-steps x (2x2 n8) x 3 terms = 96 mma/warp ---
        float acc[2][4][4];
        #pragma unroll
        for (int t = 0; t < 2; t++)
            #pragma unroll
            for (int j = 0; j < 4; j++)
                #pragma unroll
                for (int i = 0; i < 4; i++) acc[t][j][i] = 0.0f;

        const uint32_t aHi = sb + (uint32_t)(buf * 2 * ABUF) + a_off;
        const uint32_t aLo = aHi + ABUF;
        #pragma unroll
        for (int t = 0; t < 2; t++) {
            #pragma unroll
            for (int s = 0; s < 4; s++) {
                uint32_t ah[4], al[4];
                const uint32_t ao = (uint32_t)(t * 16 * STRIDE_A + s * 32);
                LDSM_X4(ah, aHi + ao);
                LDSM_X4(al, aLo + ao);
                #pragma unroll
                for (int p = 0; p < 2; p++) {
                    uint32_t bl[4];
                    LDSM_X4_T(bl, bLo + (uint32_t)(s * 16 * STRIDE_B + p * 32));
                    MMA_BF16(acc[t][2 * p],     ah, bhr[s][p][0], bhr[s][p][1]);
                    MMA_BF16(acc[t][2 * p + 1], ah, bhr[s][p][2], bhr[s][p][3]);
                    MMA_BF16(acc[t][2 * p],     ah, bl[0], bl[1]);
                    MMA_BF16(acc[t][2 * p + 1], ah, bl[2], bl[3]);
                    MMA_BF16(acc[t][2 * p],     al, bhr[s][p][0], bhr[s][p][1]);
                    MMA_BF16(acc[t][2 * p + 1], al, bhr[s][p][2], bhr[s][p][3]);
                }
            }
        }

        // --- epilogue: shfl pair-swap -> red.global.add.v4 ---
        {
            const int m0 = mt << 7;
            #pragma unroll
            for (int t = 0; t < 2; t++) {
                const int orow = out_map[kM + m0 + er0 + t * 16];
                float* obase = out + (size_t)orow * COUT + nh * 32 + q0;
                #pragma unroll
                for (int j = 0; j < 4; j++) {
                    float* c = acc[t][j];
                    const float t0 = __shfl_xor_sync(0xFFFFFFFFu, c[0], 1);
                    const float t1 = __shfl_xor_sync(0xFFFFFFFFu, c[1], 1);
                    const float t2 = __shfl_xor_sync(0xFFFFFFFFu, c[2], 1);
                    const float t3 = __shfl_xor_sync(0xFFFFFFFFu, c[3], 1);
                    const float v0 = odd ? t2 : c[0];
                    const float v1 = odd ? t3 : c[1];
                    const float v2 = odd ? c[2] : t0;
                    const float v3 = odd ? c[3] : t1;
                    red_add_v4(obase + 8 * j, v0, v1, v2, v3);
                }
            }
        }
        __syncthreads();   // gather(nxt) visible to all; this tile's LDSM done
        mt = nxt;
        buf ^= 1;
    }
}

extern "C" void kernel_launch(void* const* d_in, const int* in_sizes, int n_in,
                              void* d_out, int out_size)
{
    const float* x       = (const float*)d_in[0];
    const float* W       = (const float*)d_in[1];
    const int*   in_map  = (const int*)d_in[2];
    const int*   out_map = (const int*)d_in[3];
    float*       out     = (float*)d_out;

    const int K = in_sizes[1] / (CIN * COUT);   // 27
    const int M = in_sizes[2] / K;              // 65536

    static bool attr_set = false;
    if (!attr_set) {
        cudaFuncSetAttribute(sparse_conv_mma2,
                             cudaFuncAttributeMaxDynamicSharedMemorySize, SM_TOTAL);
        attr_set = true;
    }

    cudaMemsetAsync(d_out, 0, (size_t)out_size * sizeof(float), 0);

    dim3 grid(CTAS_X, K);
    sparse_conv_mma2<<<grid, THREADS, SM_TOTAL>>>(x, W, in_map, out_map, out, M);
}